// round 9
// baseline (speedup 1.0000x reference)
#include <cuda_runtime.h>
#include <math_constants.h>

#define NN 50000
#define EE 800000
#define CC 128

// ---------------- scratch (static device globals: allocation-free) ----------
__device__ int   g_is64;
__device__ int   g_deg[NN];
__device__ int   g_off[NN + 1];
__device__ int   g_cur[NN];
__device__ int   g_src[EE];
__device__ __align__(16) float g_maxd[(size_t)NN * CC];

// ---------------- dtype detection -------------------------------------------
// int64 little-endian indices < 50000 -> every odd 32-bit word is 0.
// Genuine int32 random indices in [0,50000): 64 consecutive zero odd-words
// is impossible. One thread, ~128 loads.
__global__ void k_detect(const int* __restrict__ ei32) {
    if (threadIdx.x == 0 && blockIdx.x == 0) {
        int acc = 0;
        #pragma unroll 8
        for (int i = 0; i < 64; i++) acc |= ei32[2 * i + 1];
        g_is64 = (acc == 0) ? 1 : 0;
    }
}

__device__ __forceinline__ unsigned load_idx(const void* ei, int pos, int is64) {
    if (is64) return (unsigned)((const long long*)ei)[pos];
    return (unsigned)((const int*)ei)[pos];
}

// ---------------- CSR build -------------------------------------------------
__global__ void k_zero_deg() {
    int i = blockIdx.x * blockDim.x + threadIdx.x;
    if (i < NN) g_deg[i] = 0;
}

__global__ void k_hist(const void* __restrict__ ei) {
    int is64 = g_is64;
    int e = blockIdx.x * blockDim.x + threadIdx.x;
    if (e < EE) {
        unsigned dst = load_idx(ei, EE + e, is64);
        if (dst < NN) atomicAdd(&g_deg[dst], 1);
    }
}

// ---------------- fast single-block scan ------------------------------------
// Phase 1: each thread serially reduces a contiguous 49-elem chunk (MLP loads).
// Phase 2: shfl warp scan of 1024 partials + warp-sum scan (2 barriers total).
// Phase 3: serial writeback of running prefix per chunk.
#define SCAN_CHUNK 49   // 1024 * 49 = 50176 >= 50000
__global__ void k_scan() {
    __shared__ int wsum[32];
    int tid  = threadIdx.x;
    int lane = tid & 31, warp = tid >> 5;
    int b0   = tid * SCAN_CHUNK;

    int s = 0;
    #pragma unroll
    for (int i = 0; i < SCAN_CHUNK; i++) {
        int idx = b0 + i;
        if (idx < NN) s += g_deg[idx];
    }

    // inclusive warp scan of per-thread sums
    int v = s;
    #pragma unroll
    for (int o = 1; o < 32; o <<= 1) {
        int t = __shfl_up_sync(0xFFFFFFFFu, v, o);
        if (lane >= o) v += t;
    }
    if (lane == 31) wsum[warp] = v;
    __syncthreads();
    if (warp == 0) {
        int w = wsum[lane];
        #pragma unroll
        for (int o = 1; o < 32; o <<= 1) {
            int t = __shfl_up_sync(0xFFFFFFFFu, w, o);
            if (lane >= o) w += t;
        }
        wsum[lane] = w;
    }
    __syncthreads();

    int excl = v - s + (warp ? wsum[warp - 1] : 0);  // exclusive prefix of chunk

    int run = excl;
    #pragma unroll
    for (int i = 0; i < SCAN_CHUNK; i++) {
        int idx = b0 + i;
        if (idx < NN) {
            int d = g_deg[idx];
            g_off[idx] = run;
            g_cur[idx] = run;
            run += d;
        }
    }
    // last thread's chunk starts >= NN, so its run == excl == grand total
    if (tid == 1023) g_off[NN] = run;
}

__global__ void k_scatter(const void* __restrict__ ei) {
    int is64 = g_is64;
    int e = blockIdx.x * blockDim.x + threadIdx.x;
    if (e < EE) {
        unsigned src = load_idx(ei, e, is64);
        unsigned dst = load_idx(ei, EE + e, is64);
        if (src < NN && dst < NN) {
            int p = atomicAdd(&g_cur[dst], 1);
            if (p >= 0 && p < EE) g_src[p] = (int)src;
        }
    }
}

// ---------------- warp-per-node segment max --------------------------------
// Each warp owns one node: lane holds a float4 (4 of the 128 channels).
__global__ void k_nodemax(const float* __restrict__ x) {
    int gw   = (blockIdx.x * blockDim.x + threadIdx.x) >> 5;
    int lane = threadIdx.x & 31;
    if (gw >= NN) return;

    const float4* x4 = (const float4*)x;
    float4 xd = x4[gw * 32 + lane];

    float4 m = make_float4(-CUDART_INF_F, -CUDART_INF_F, -CUDART_INF_F, -CUDART_INF_F);
    int beg = g_off[gw];
    int end = g_off[gw + 1];

    for (int e = beg; e < end; e++) {
        unsigned s = (unsigned)g_src[e];       // uniform across warp -> broadcast
        if (s >= NN) continue;
        float4 xs = x4[s * 32 + lane];
        m.x = fmaxf(m.x, xs.x - xd.x);
        m.y = fmaxf(m.y, xs.y - xd.y);
        m.z = fmaxf(m.z, xs.z - xd.z);
        m.w = fmaxf(m.w, xs.w - xd.w);
    }
    if (beg >= end) m = make_float4(0.f, 0.f, 0.f, 0.f);
    ((float4*)g_maxd)[gw * 32 + lane] = m;
}

// ---------------- fused concat-GEMM: out = x@W_top + maxd@W_bot + b --------
// 128x128 block tile, BK=16, 256 threads, 8x8 register tile per thread.
// Two k-passes (x then g_maxd) — pointer is loop-invariant per pass.
// NOTE: k ascends monotonically -> accumulation order matches reference
// bit-exactly (rel_err was 0.0). Do not reorder.
__global__ __launch_bounds__(256) void k_gemm(
    const float* __restrict__ x,
    const float* __restrict__ W,
    const float* __restrict__ b,
    float* __restrict__ out)
{
    __shared__ float As[16][132];   // padded: transpose-store conflict relief
    __shared__ float Bs[16][128];

    int tid  = threadIdx.x;
    int row0 = blockIdx.x * 128;
    int ty = tid / 16, tx = tid % 16;     // 16x16 thread grid
    int ar = tid >> 2, ac = tid & 3;      // A-load: rows {ar, ar+64}, k-chunk ac
    int bkr = tid >> 5, bc = tid & 31;    // B-load: kk rows {bkr, bkr+8}, col chunk bc

    float acc[8][8];
    #pragma unroll
    for (int i = 0; i < 8; i++)
        #pragma unroll
        for (int j = 0; j < 8; j++) acc[i][j] = 0.f;

    #pragma unroll 1
    for (int pass = 0; pass < 2; pass++) {
        const float* Asrc = (pass == 0) ? x : (const float*)g_maxd;
        int kbase = pass * 128;

        #pragma unroll 1
        for (int koff = 0; koff < 128; koff += 16) {
            // A tile (128 rows x 16 k), stored transposed As[kk][row]
            #pragma unroll
            for (int s = 0; s < 2; s++) {
                int r  = ar + s * 64;
                int gr = row0 + r;
                float4 v = make_float4(0.f, 0.f, 0.f, 0.f);
                if (gr < NN)
                    v = *(const float4*)(Asrc + (size_t)gr * 128 + koff + ac * 4);
                As[ac * 4 + 0][r] = v.x;
                As[ac * 4 + 1][r] = v.y;
                As[ac * 4 + 2][r] = v.z;
                As[ac * 4 + 3][r] = v.w;
            }
            // B tile (16 k x 128 cols), natural layout
            #pragma unroll
            for (int s = 0; s < 2; s++) {
                int kk = bkr + s * 8;
                *(float4*)&Bs[kk][bc * 4] =
                    *(const float4*)(W + (size_t)(kbase + koff + kk) * 128 + bc * 4);
            }
            __syncthreads();

            #pragma unroll
            for (int kk = 0; kk < 16; kk++) {
                float a[8], bb[8];
                #pragma unroll
                for (int i = 0; i < 8; i++) a[i] = As[kk][ty * 8 + i];
                #pragma unroll
                for (int j = 0; j < 8; j++) bb[j] = Bs[kk][tx * 8 + j];
                #pragma unroll
                for (int i = 0; i < 8; i++)
                    #pragma unroll
                    for (int j = 0; j < 8; j++)
                        acc[i][j] += a[i] * bb[j];
            }
            __syncthreads();
        }
    }

    float bias[8];
    #pragma unroll
    for (int j = 0; j < 8; j++) bias[j] = b[tx * 8 + j];

    #pragma unroll
    for (int i = 0; i < 8; i++) {
        int gr = row0 + ty * 8 + i;
        if (gr < NN) {
            #pragma unroll
            for (int j = 0; j < 8; j += 4) {
                float4 v;
                v.x = acc[i][j + 0] + bias[j + 0];
                v.y = acc[i][j + 1] + bias[j + 1];
                v.z = acc[i][j + 2] + bias[j + 2];
                v.w = acc[i][j + 3] + bias[j + 3];
                *(float4*)(out + (size_t)gr * 128 + tx * 8 + j) = v;
            }
        }
    }
}

// ---------------- launch ----------------------------------------------------
extern "C" void kernel_launch(void* const* d_in, const int* in_sizes, int n_in,
                              void* d_out, int out_size) {
    // Identify inputs by element count (all four are distinct) — immune to
    // any metadata ordering surprises.
    const float* x  = nullptr;   // 50000*128   = 6400000 f32
    const void*  ei = nullptr;   // 2*800000    = 1600000 elems (int32 OR int64)
    const float* W  = nullptr;   // 256*128     = 32768   f32
    const float* b  = nullptr;   // 128         = 128     f32
    for (int i = 0; i < n_in; i++) {
        switch (in_sizes[i]) {
            case NN * CC:     x  = (const float*)d_in[i]; break;
            case 2 * EE:      ei = d_in[i];               break;
            case 2 * CC * CC: W  = (const float*)d_in[i]; break;
            case CC:          b  = (const float*)d_in[i]; break;
            default: break;
        }
    }
    if (!x)  x  = (const float*)d_in[0];
    if (!ei) ei = d_in[1];
    if (!W)  W  = (const float*)d_in[2];
    if (!b)  b  = (const float*)d_in[3];
    float* out = (float*)d_out;

    k_detect<<<1, 32>>>((const int*)ei);
    k_zero_deg<<<(NN + 255) / 256, 256>>>();
    k_hist<<<EE / 256, 256>>>(ei);
    k_scan<<<1, 1024>>>();
    k_scatter<<<EE / 256, 256>>>(ei);
    k_nodemax<<<(NN + 7) / 8, 256>>>(x);          // 8 warps/block, warp-per-node
    k_gemm<<<(NN + 127) / 128, 256>>>(x, W, b, out);
}

// round 11
// speedup vs baseline: 1.3614x; 1.3614x over previous
#include <cuda_runtime.h>
#include <math_constants.h>

#define NN 50000
#define EE 800000
#define CC 128

// ---------------- scratch (static device globals: allocation-free) ----------
__device__ int   g_is64;
__device__ __align__(16) int g_deg[NN];
__device__ __align__(16) int g_off[NN + 4];   // +pad, [NN] = total
__device__ __align__(16) int g_cur[NN];
__device__ int   g_src[EE];
__device__ __align__(16) float g_maxd[(size_t)NN * CC];

// ---------------- zero degrees + dtype detection (merged) -------------------
// int64 little-endian indices < 50000 -> every odd 32-bit word is 0.
// Genuine int32 random indices: 128 consecutive zero odd-words impossible.
__global__ void k_zero_detect(const int* __restrict__ ei32) {
    int i = blockIdx.x * blockDim.x + threadIdx.x;
    if (i < NN) g_deg[i] = 0;
    if (blockIdx.x == 0 && threadIdx.x < 32) {
        int t = threadIdx.x;
        int acc = ei32[2 * t + 1] | ei32[2 * (t + 32) + 1] |
                  ei32[2 * (t + 64) + 1] | ei32[2 * (t + 96) + 1];
        unsigned any = __ballot_sync(0xFFFFFFFFu, acc != 0);
        if (t == 0) g_is64 = (any == 0u) ? 1 : 0;
    }
}

__device__ __forceinline__ unsigned load_idx(const void* ei, int pos, int is64) {
    if (is64) return (unsigned)((const long long*)ei)[pos];
    return (unsigned)((const int*)ei)[pos];
}

// ---------------- CSR build -------------------------------------------------
__global__ void k_hist(const void* __restrict__ ei) {
    int is64 = g_is64;
    int e = blockIdx.x * blockDim.x + threadIdx.x;
    if (e < EE) {
        unsigned dst = load_idx(ei, EE + e, is64);
        if (dst < NN) atomicAdd(&g_deg[dst], 1);
    }
}

// ---------------- latency-optimized single-block scan ------------------------
// 512 threads (reg cap 128/thread), 25 int4s per thread register-cached
// (MLP=25), shfl block scan of per-thread sums (2 barriers), pure-ALU
// writeback with int4 stores. No serial global reload chain anywhere.
#define SCAN_T 512
#define SC4    25                 // int4s per thread; 512*25*4 = 51200 >= 50000
#define N4     (NN / 4)           // 12500 int4s exactly (50000 % 4 == 0)
__global__ __launch_bounds__(SCAN_T) void k_scan() {
    __shared__ int wsum[16];
    int tid  = threadIdx.x;
    int lane = tid & 31, warp = tid >> 5;   // 16 warps
    int base4 = tid * SC4;

    const int4* d4 = (const int4*)g_deg;
    int4 v[SC4];
    #pragma unroll
    for (int i = 0; i < SC4; i++) {
        int idx4 = base4 + i;
        v[i] = (idx4 < N4) ? d4[idx4] : make_int4(0, 0, 0, 0);
    }

    int s = 0;
    #pragma unroll
    for (int i = 0; i < SC4; i++) s += v[i].x + v[i].y + v[i].z + v[i].w;

    // inclusive warp scan of per-thread sums
    int incl = s;
    #pragma unroll
    for (int o = 1; o < 32; o <<= 1) {
        int t = __shfl_up_sync(0xFFFFFFFFu, incl, o);
        if (lane >= o) incl += t;
    }
    if (lane == 31) wsum[warp] = incl;
    __syncthreads();
    if (warp == 0 && lane < 16) {
        int w = wsum[lane];
        #pragma unroll
        for (int o = 1; o < 16; o <<= 1) {
            int t = __shfl_up_sync(0x0000FFFFu, w, o);
            if (lane >= o) w += t;
        }
        wsum[lane] = w;
    }
    __syncthreads();

    int run = incl - s + (warp ? wsum[warp - 1] : 0);  // exclusive thread prefix

    int4* o4 = (int4*)g_off;
    int4* c4 = (int4*)g_cur;
    #pragma unroll
    for (int i = 0; i < SC4; i++) {
        int idx4 = base4 + i;
        if (idx4 < N4) {
            int4 d = v[i];
            int4 o;
            o.x = run;
            o.y = o.x + d.x;
            o.z = o.y + d.y;
            o.w = o.z + d.z;
            o4[idx4] = o;
            c4[idx4] = o;
            run = o.w + d.w;
        }
    }
    // last thread's chunk starts beyond NN, so its run == grand total
    if (tid == SCAN_T - 1) g_off[NN] = run;
}

__global__ void k_scatter(const void* __restrict__ ei) {
    int is64 = g_is64;
    int e = blockIdx.x * blockDim.x + threadIdx.x;
    if (e < EE) {
        unsigned src = load_idx(ei, e, is64);
        unsigned dst = load_idx(ei, EE + e, is64);
        if (src < NN && dst < NN) {
            int p = atomicAdd(&g_cur[dst], 1);
            if (p >= 0 && p < EE) g_src[p] = (int)src;
        }
    }
}

// ---------------- warp-per-node segment max --------------------------------
// Each warp owns one node: lane holds a float4 (4 of the 128 channels).
__global__ void k_nodemax(const float* __restrict__ x) {
    int gw   = (blockIdx.x * blockDim.x + threadIdx.x) >> 5;
    int lane = threadIdx.x & 31;
    if (gw >= NN) return;

    const float4* x4 = (const float4*)x;
    float4 xd = x4[gw * 32 + lane];

    float4 m = make_float4(-CUDART_INF_F, -CUDART_INF_F, -CUDART_INF_F, -CUDART_INF_F);
    int beg = g_off[gw];
    int end = g_off[gw + 1];

    for (int e = beg; e < end; e++) {
        unsigned s = (unsigned)g_src[e];       // uniform across warp -> broadcast
        if (s >= NN) continue;
        float4 xs = x4[s * 32 + lane];
        m.x = fmaxf(m.x, xs.x - xd.x);
        m.y = fmaxf(m.y, xs.y - xd.y);
        m.z = fmaxf(m.z, xs.z - xd.z);
        m.w = fmaxf(m.w, xs.w - xd.w);
    }
    if (beg >= end) m = make_float4(0.f, 0.f, 0.f, 0.f);
    ((float4*)g_maxd)[gw * 32 + lane] = m;
}

// ---------------- fused concat-GEMM: out = x@W_top + maxd@W_bot + b --------
// 128x128 block tile, BK=16, 256 threads, 8x8 register tile per thread.
// NOTE: k ascends monotonically -> accumulation order matches reference
// bit-exactly (rel_err was 0.0). Do not reorder.
__global__ __launch_bounds__(256) void k_gemm(
    const float* __restrict__ x,
    const float* __restrict__ W,
    const float* __restrict__ b,
    float* __restrict__ out)
{
    __shared__ float As[16][132];   // padded: transpose-store conflict relief
    __shared__ float Bs[16][128];

    int tid  = threadIdx.x;
    int row0 = blockIdx.x * 128;
    int ty = tid / 16, tx = tid % 16;     // 16x16 thread grid
    int ar = tid >> 2, ac = tid & 3;      // A-load: rows {ar, ar+64}, k-chunk ac
    int bkr = tid >> 5, bc = tid & 31;    // B-load: kk rows {bkr, bkr+8}, col chunk bc

    float acc[8][8];
    #pragma unroll
    for (int i = 0; i < 8; i++)
        #pragma unroll
        for (int j = 0; j < 8; j++) acc[i][j] = 0.f;

    #pragma unroll 1
    for (int pass = 0; pass < 2; pass++) {
        const float* Asrc = (pass == 0) ? x : (const float*)g_maxd;
        int kbase = pass * 128;

        #pragma unroll 1
        for (int koff = 0; koff < 128; koff += 16) {
            // A tile (128 rows x 16 k), stored transposed As[kk][row]
            #pragma unroll
            for (int s = 0; s < 2; s++) {
                int r  = ar + s * 64;
                int gr = row0 + r;
                float4 v = make_float4(0.f, 0.f, 0.f, 0.f);
                if (gr < NN)
                    v = *(const float4*)(Asrc + (size_t)gr * 128 + koff + ac * 4);
                As[ac * 4 + 0][r] = v.x;
                As[ac * 4 + 1][r] = v.y;
                As[ac * 4 + 2][r] = v.z;
                As[ac * 4 + 3][r] = v.w;
            }
            // B tile (16 k x 128 cols), natural layout
            #pragma unroll
            for (int s = 0; s < 2; s++) {
                int kk = bkr + s * 8;
                *(float4*)&Bs[kk][bc * 4] =
                    *(const float4*)(W + (size_t)(kbase + koff + kk) * 128 + bc * 4);
            }
            __syncthreads();

            #pragma unroll
            for (int kk = 0; kk < 16; kk++) {
                float a[8], bb[8];
                #pragma unroll
                for (int i = 0; i < 8; i++) a[i] = As[kk][ty * 8 + i];
                #pragma unroll
                for (int j = 0; j < 8; j++) bb[j] = Bs[kk][tx * 8 + j];
                #pragma unroll
                for (int i = 0; i < 8; i++)
                    #pragma unroll
                    for (int j = 0; j < 8; j++)
                        acc[i][j] += a[i] * bb[j];
            }
            __syncthreads();
        }
    }

    float bias[8];
    #pragma unroll
    for (int j = 0; j < 8; j++) bias[j] = b[tx * 8 + j];

    #pragma unroll
    for (int i = 0; i < 8; i++) {
        int gr = row0 + ty * 8 + i;
        if (gr < NN) {
            #pragma unroll
            for (int j = 0; j < 8; j += 4) {
                float4 v;
                v.x = acc[i][j + 0] + bias[j + 0];
                v.y = acc[i][j + 1] + bias[j + 1];
                v.z = acc[i][j + 2] + bias[j + 2];
                v.w = acc[i][j + 3] + bias[j + 3];
                *(float4*)(out + (size_t)gr * 128 + tx * 8 + j) = v;
            }
        }
    }
}

// ---------------- launch ----------------------------------------------------
extern "C" void kernel_launch(void* const* d_in, const int* in_sizes, int n_in,
                              void* d_out, int out_size) {
    // Identify inputs by element count (all four are distinct) — immune to
    // any metadata ordering surprises.
    const float* x  = nullptr;   // 50000*128   = 6400000 f32
    const void*  ei = nullptr;   // 2*800000    = 1600000 elems (int32 OR int64)
    const float* W  = nullptr;   // 256*128     = 32768   f32
    const float* b  = nullptr;   // 128         = 128     f32
    for (int i = 0; i < n_in; i++) {
        switch (in_sizes[i]) {
            case NN * CC:     x  = (const float*)d_in[i]; break;
            case 2 * EE:      ei = d_in[i];               break;
            case 2 * CC * CC: W  = (const float*)d_in[i]; break;
            case CC:          b  = (const float*)d_in[i]; break;
            default: break;
        }
    }
    if (!x)  x  = (const float*)d_in[0];
    if (!ei) ei = d_in[1];
    if (!W)  W  = (const float*)d_in[2];
    if (!b)  b  = (const float*)d_in[3];
    float* out = (float*)d_out;

    k_zero_detect<<<(NN + 255) / 256, 256>>>((const int*)ei);
    k_hist<<<EE / 256, 256>>>(ei);
    k_scan<<<1, SCAN_T>>>();
    k_scatter<<<EE / 256, 256>>>(ei);
    k_nodemax<<<(NN + 7) / 8, 256>>>(x);          // 8 warps/block, warp-per-node
    k_gemm<<<(NN + 127) / 128, 256>>>(x, W, b, out);
}